// round 4
// baseline (speedup 1.0000x reference)
#include <cuda_runtime.h>
#include <cuda_fp16.h>
#include <cstdint>

// ---------------------------------------------------------------------------
// Problem constants
// ---------------------------------------------------------------------------
#define NSAMP 4096
#define DIM   1024     // IN == HID == DIM_T
#define LAYERS 4
#define GROWS (LAYERS*4*DIM)       // 16384 stacked gate rows
#define NSTEP (NSAMP*LAYERS)       // 16384 sequential steps

// ---------------------------------------------------------------------------
// Scratch (static device globals; no runtime allocation)
// ---------------------------------------------------------------------------
__device__ float g_PE [(size_t)NSAMP*DIM];
__device__ float g_T1 [(size_t)NSAMP*DIM];
__device__ float g_EMB[(size_t)NSAMP*DIM];
__device__ float g_XP [(size_t)NSAMP*DIM];
__device__ float g_R  [(size_t)GROWS*NSAMP];   // 256 MB: R[row, i]
__device__ float g_H  [(size_t)NSAMP*DIM];
__device__ float g_BS [GROWS];
// Double-buffered tagged h-exchange: buffer (g&1) holds {tag=g, h bits}.
__device__ unsigned long long g_hpub[2*DIM];

// ---------------------------------------------------------------------------
// Sinusoidal positional embedding
// ---------------------------------------------------------------------------
__global__ void pe_kernel(const int* __restrict__ ts, float* __restrict__ PE) {
    int i = blockIdx.x;
    float t = (float)ts[i];
    for (int d = threadIdx.x; d < DIM/2; d += blockDim.x) {
        float f = expf((float)d * (-9.210340371976184f / (float)(DIM/2 - 1)));
        float a = t * f;
        PE[(size_t)i*DIM + d]          = sinf(a);
        PE[(size_t)i*DIM + DIM/2 + d]  = cosf(a);
    }
}

__global__ void bias_kernel(const float* __restrict__ bih, const float* __restrict__ bhh,
                            float* __restrict__ out) {
    int idx = blockIdx.x*blockDim.x + threadIdx.x;
    if (idx < GROWS) out[idx] = bih[idx] + bhh[idx];
}

__global__ void reset_kernel() {
    int idx = blockIdx.x*blockDim.x + threadIdx.x;
    if (idx < 2*DIM) g_hpub[idx] = 0ULL;   // tag 0, h = 0.0f
}

// ---------------------------------------------------------------------------
// Generic NT GEMM: C[m,n] = sum_k A[m,k]*B[n,k] (+biasM[m]) (+biasN[n]) (+add[m,n]) (silu)
// BM=BN=128, BK=16, 256 threads, 8x8 per thread, double-buffered SMEM.
// All shapes are multiples of the tiles; no bounds checks.
// ---------------------------------------------------------------------------
__global__ __launch_bounds__(256, 2)
void gemm_nt(const float* __restrict__ A, const float* __restrict__ B,
             float* __restrict__ C, int M, int N, int K,
             const float* __restrict__ biasM, const float* __restrict__ biasN,
             const float* __restrict__ addMN, int do_silu)
{
    const int BM = 128, BK = 16;
    __shared__ float As[2][16][128+8];
    __shared__ float Bs[2][16][128+8];

    const int tid = threadIdx.x;
    const int m0 = blockIdx.y * BM, n0 = blockIdx.x * BM;
    const int tx = tid & 15, ty = tid >> 4;

    float4 aF[2], bF[2];

    #pragma unroll
    for (int i = 0; i < 2; i++) {
        int f = tid + i*256;
        int row = f >> 2, c4 = (f & 3) * 4;
        aF[i] = *(const float4*)&A[(size_t)(m0+row)*K + c4];
        bF[i] = *(const float4*)&B[(size_t)(n0+row)*K + c4];
    }
    #pragma unroll
    for (int i = 0; i < 2; i++) {
        int f = tid + i*256;
        int row = f >> 2, c4 = (f & 3) * 4;
        As[0][c4+0][row] = aF[i].x; As[0][c4+1][row] = aF[i].y;
        As[0][c4+2][row] = aF[i].z; As[0][c4+3][row] = aF[i].w;
        Bs[0][c4+0][row] = bF[i].x; Bs[0][c4+1][row] = bF[i].y;
        Bs[0][c4+2][row] = bF[i].z; Bs[0][c4+3][row] = bF[i].w;
    }
    __syncthreads();

    float acc[8][8];
    #pragma unroll
    for (int i = 0; i < 8; i++)
        #pragma unroll
        for (int j = 0; j < 8; j++) acc[i][j] = 0.f;

    const int nk = K / BK;
    for (int kt = 0; kt < nk; kt++) {
        const int cur = kt & 1;
        if (kt + 1 < nk) {
            int k0 = (kt+1)*BK;
            #pragma unroll
            for (int i = 0; i < 2; i++) {
                int f = tid + i*256;
                int row = f >> 2, c4 = (f & 3) * 4;
                aF[i] = *(const float4*)&A[(size_t)(m0+row)*K + k0 + c4];
                bF[i] = *(const float4*)&B[(size_t)(n0+row)*K + k0 + c4];
            }
        }
        #pragma unroll
        for (int k = 0; k < BK; k++) {
            float a[8], b[8];
            *(float4*)&a[0] = *(const float4*)&As[cur][k][ty*8];
            *(float4*)&a[4] = *(const float4*)&As[cur][k][ty*8+4];
            *(float4*)&b[0] = *(const float4*)&Bs[cur][k][tx*8];
            *(float4*)&b[4] = *(const float4*)&Bs[cur][k][tx*8+4];
            #pragma unroll
            for (int i = 0; i < 8; i++)
                #pragma unroll
                for (int j = 0; j < 8; j++)
                    acc[i][j] += a[i] * b[j];
        }
        if (kt + 1 < nk) {
            const int nxt = cur ^ 1;
            #pragma unroll
            for (int i = 0; i < 2; i++) {
                int f = tid + i*256;
                int row = f >> 2, c4 = (f & 3) * 4;
                As[nxt][c4+0][row] = aF[i].x; As[nxt][c4+1][row] = aF[i].y;
                As[nxt][c4+2][row] = aF[i].z; As[nxt][c4+3][row] = aF[i].w;
                Bs[nxt][c4+0][row] = bF[i].x; Bs[nxt][c4+1][row] = bF[i].y;
                Bs[nxt][c4+2][row] = bF[i].z; Bs[nxt][c4+3][row] = bF[i].w;
            }
            __syncthreads();
        }
    }

    #pragma unroll
    for (int i = 0; i < 8; i++) {
        int m = m0 + ty*8 + i;
        float bm = biasM ? biasM[m] : 0.f;
        #pragma unroll
        for (int j = 0; j < 8; j++) {
            int n = n0 + tx*8 + j;
            float v = acc[i][j] + bm;
            if (biasN) v += biasN[n];
            if (addMN) v += addMN[(size_t)m*N + n];
            if (do_silu) v = v / (1.f + __expf(-v));
            C[(size_t)m*N + n] = v;
        }
    }
}

// ---------------------------------------------------------------------------
// Persistent sequential-scan kernel.
// 147 CTAs x 128 threads. CTA k owns h indices [7k, min(7k+7,1024)).
// SMEM: fp16 Whh rows for 4 layers (permuted), fp16 h broadcast, dot/A scratch.
// ---------------------------------------------------------------------------
#define SCAN_CTAS 147
#define SCAN_TPB  128
#define WS_HALFS  (LAYERS*28*1024)            // 114688 halves
#define WS_BYTES  (WS_HALFS*2)                // 229376 B
#define SCAN_SMEM (WS_BYTES + 2048 + (28+56)*4)   // + h_sm(fp16) + gdot + ga[2]

__device__ __forceinline__ float tanh_fast(float x) {
    float cx = fminf(fmaxf(x, -15.f), 15.f);
    float e  = __expf(2.f * cx);
    return __fdividef(e - 1.f, e + 1.f);
}
__device__ __forceinline__ float sigmoid_fast(float x) {
    return __fdividef(1.f, 1.f + __expf(-x));
}

__global__ __launch_bounds__(SCAN_TPB, 1)
void scan_kernel(const float* __restrict__ Whh, const float* __restrict__ R,
                 float* __restrict__ Hbuf)
{
    extern __shared__ unsigned char smem[];
    __half* ws   = (__half*)smem;                         // [(l*28+rl)*1024 + perm]
    __half* h_sm = (__half*)(smem + WS_BYTES);            // [1024] permuted
    float*  gdot = (float*)(smem + WS_BYTES + 2048);      // [28]
    float*  ga   = gdot + 28;                             // [2][28]

    const int cta = blockIdx.x, tid = threadIdx.x;
    const int j0  = cta * 7;
    const int nj  = (j0 + 7 <= DIM) ? 7 : (DIM - j0);     // last CTA: 2

    // ---- fill SMEM weights (fp16, permuted: lane reads wr[m8*256+lane*8+b] = k(lane*32+m8*8+b))
    for (int p = tid; p < WS_HALFS; p += SCAN_TPB) {
        int rowblk = p >> 10;                   // l*28 + rl
        int l  = rowblk / 28, rl = rowblk - l*28;
        int off = p & 1023;
        int m8 = off >> 8, ln = (off >> 3) & 31, b = off & 7;
        int q = rl / 7, u = rl - q*7;
        float v = 0.f;
        if (u < nj) {
            int k = ln*32 + m8*8 + b;
            v = Whh[((size_t)l*4*DIM + q*DIM + j0 + u)*DIM + k];
        }
        ws[p] = __float2half(v);
    }
    __syncthreads();

    const int w = tid >> 5, lane = tid & 31;
    float cst = 0.f;                             // c state (warp0 lane u only)
    volatile unsigned long long* hp = (volatile unsigned long long*)g_hpub;

    // prefetch helpers
    int pf_q = 0, pf_u = 0;
    bool pf_act = (tid < 28);
    if (pf_act) { pf_q = tid / 7; pf_u = tid - pf_q*7; pf_act = (pf_u < nj); }

    #pragma unroll 1
    for (int g = 1; g <= NSTEP; ++g) {
        const int s = g - 1;
        const int i = s >> 2, l = s & 3;

        // ---- issue R prefetch into a register (latency hides behind the poll)
        float aval = 0.f;
        if (pf_act)
            aval = R[((size_t)(l*4*DIM + pf_q*DIM + j0 + pf_u))*NSAMP + i];

        // ---- poll h (8 tagged entries/thread) from buffer s&1; accept tag >= s.
        // Double buffering guarantees buffer (s&1) cannot advance past tag s
        // until every CTA (including us) has consumed tag s.
        {
            const int e0 = (s & 1)*DIM + tid * 8;
            unsigned long long vb[8];
            for (;;) {
                bool ok = true;
                #pragma unroll
                for (int jj = 0; jj < 8; jj++) vb[jj] = hp[e0 + jj];
                #pragma unroll
                for (int jj = 0; jj < 8; jj++)
                    ok &= ((unsigned)(vb[jj] >> 32) >= (unsigned)s);
                if (ok) break;
            }
            int base = (tid & 3)*256 + (tid >> 2)*8;   // permuted halves
            __half hh[8];
            #pragma unroll
            for (int jj = 0; jj < 8; jj++)
                hh[jj] = __float2half(__uint_as_float((unsigned)vb[jj]));
            *(uint4*)&h_sm[base] = *(uint4*)hh;
        }
        if (tid < 28) ga[(g & 1)*28 + tid] = aval;   // store after poll: LDG retired
        __syncthreads();   // B1

        // ---- load h into registers: lane owns h[lane*32 .. +32)
        float hreg[32];
        #pragma unroll
        for (int m8 = 0; m8 < 4; m8++) {
            uint4 hv = *(const uint4*)&h_sm[m8*256 + lane*8];
            const __half2* h2 = (const __half2*)&hv;
            #pragma unroll
            for (int p2 = 0; p2 < 4; p2++) {
                float2 f = __half22float2(h2[p2]);
                hreg[m8*8 + p2*2]     = f.x;
                hreg[m8*8 + p2*2 + 1] = f.y;
            }
        }

        // ---- 7 rows per warp: rl = w + 4t
        float dotv[7];
        #pragma unroll
        for (int t = 0; t < 7; t++) {
            const int rl = w + 4*t;
            const __half* wr = ws + (((size_t)l*28 + rl) << 10);
            float acc = 0.f;
            #pragma unroll
            for (int m8 = 0; m8 < 4; m8++) {
                uint4 wv = *(const uint4*)&wr[m8*256 + lane*8];
                const __half2* w2 = (const __half2*)&wv;
                #pragma unroll
                for (int p2 = 0; p2 < 4; p2++) {
                    float2 wf = __half22float2(w2[p2]);
                    acc += wf.x * hreg[m8*8 + p2*2] + wf.y * hreg[m8*8 + p2*2 + 1];
                }
            }
            dotv[t] = acc;
        }
        #pragma unroll
        for (int t = 0; t < 7; t++) {
            float v = dotv[t];
            v += __shfl_xor_sync(0xffffffffu, v, 16);
            v += __shfl_xor_sync(0xffffffffu, v, 8);
            v += __shfl_xor_sync(0xffffffffu, v, 4);
            v += __shfl_xor_sync(0xffffffffu, v, 2);
            v += __shfl_xor_sync(0xffffffffu, v, 1);
            if (lane == 0) gdot[w + 4*t] = v;
        }
        __syncthreads();   // B2

        // ---- gate math + publish (warp 0, lanes 0..nj-1)
        if (w == 0 && lane < nj) {
            const float* gav = ga + (g & 1)*28;
            float gi = gdot[lane]      + gav[lane];
            float gf = gdot[7 + lane]  + gav[7 + lane];
            float gg = gdot[14 + lane] + gav[14 + lane];
            float go = gdot[21 + lane] + gav[21 + lane];
            float I = sigmoid_fast(gi);
            float F = sigmoid_fast(gf);
            float G = tanh_fast(gg);
            cst = F * cst + I * G;
            float O = sigmoid_fast(go);
            float h = O * tanh_fast(cst);
            if (l == 3) Hbuf[(size_t)i*DIM + j0 + lane] = h;
            unsigned long long pk =
                (((unsigned long long)(unsigned)g) << 32) |
                (unsigned long long)(unsigned)__float_as_uint(h);
            hp[(g & 1)*DIM + j0 + lane] = pk;      // publish into buffer g&1
        }
        // no trailing barrier: next step's poll self-synchronizes on tags
    }
}

// ---------------------------------------------------------------------------
// Launch
// ---------------------------------------------------------------------------
extern "C" void kernel_launch(void* const* d_in, const int* in_sizes, int n_in,
                              void* d_out, int out_size)
{
    const float* x      = (const float*)d_in[0];
    const int*   ts     = (const int*)  d_in[1];
    const float* proj_w = (const float*)d_in[2];
    const float* proj_b = (const float*)d_in[3];
    const float* te_w1  = (const float*)d_in[4];
    const float* te_b1  = (const float*)d_in[5];
    const float* te_w2  = (const float*)d_in[6];
    const float* te_b2  = (const float*)d_in[7];
    const float* Wih    = (const float*)d_in[8];
    const float* Whh    = (const float*)d_in[9];
    const float* bih    = (const float*)d_in[10];
    const float* bhh    = (const float*)d_in[11];
    const float* lin_w  = (const float*)d_in[12];
    const float* lin_b  = (const float*)d_in[13];
    float* out = (float*)d_out;

    float *PE, *T1, *EMB, *XP, *R, *H, *BS;
    cudaGetSymbolAddress((void**)&PE,  g_PE);
    cudaGetSymbolAddress((void**)&T1,  g_T1);
    cudaGetSymbolAddress((void**)&EMB, g_EMB);
    cudaGetSymbolAddress((void**)&XP,  g_XP);
    cudaGetSymbolAddress((void**)&R,   g_R);
    cudaGetSymbolAddress((void**)&H,   g_H);
    cudaGetSymbolAddress((void**)&BS,  g_BS);

    cudaFuncSetAttribute(scan_kernel, cudaFuncAttributeMaxDynamicSharedMemorySize,
                         SCAN_SMEM);

    // 1) sinusoidal PE
    pe_kernel<<<NSAMP, 128>>>(ts, PE);
    // 2) T1 = silu(PE @ te_w1^T + te_b1)
    gemm_nt<<<dim3(DIM/128, NSAMP/128), 256>>>(PE, te_w1, T1, NSAMP, DIM, DIM,
                                               nullptr, te_b1, nullptr, 1);
    // 3) EMB = T1 @ te_w2^T + te_b2
    gemm_nt<<<dim3(DIM/128, NSAMP/128), 256>>>(T1, te_w2, EMB, NSAMP, DIM, DIM,
                                               nullptr, te_b2, nullptr, 0);
    // 4) XP = x @ proj_w^T + proj_b + EMB
    gemm_nt<<<dim3(DIM/128, NSAMP/128), 256>>>(x, proj_w, XP, NSAMP, DIM, DIM,
                                               nullptr, proj_b, EMB, 0);
    // 5) stacked gate bias
    bias_kernel<<<GROWS/256, 256>>>(bih, bhh, BS);
    // 6) R = Wih_stack @ XP^T + bias   (16384 x 4096 x 1024)
    gemm_nt<<<dim3(NSAMP/128, GROWS/128), 256>>>(Wih, XP, R, GROWS, NSAMP, DIM,
                                                 BS, nullptr, nullptr, 0);
    // 7) reset tagged h buffers (graph-replay safe)
    reset_kernel<<<(2*DIM+255)/256, 256>>>();
    // 8) persistent sequential scan
    scan_kernel<<<SCAN_CTAS, SCAN_TPB, SCAN_SMEM>>>(Whh, R, H);
    // 9) out = H @ lin_w^T + lin_b
    gemm_nt<<<dim3(DIM/128, NSAMP/128), 256>>>(H, lin_w, out, NSAMP, DIM, DIM,
                                               nullptr, lin_b, nullptr, 0);
}

// round 5
// speedup vs baseline: 1.5988x; 1.5988x over previous
#include <cuda_runtime.h>
#include <cuda_fp16.h>
#include <cstdint>

// ---------------------------------------------------------------------------
// Problem constants
// ---------------------------------------------------------------------------
#define NSAMP 4096
#define DIM   1024     // IN == HID == DIM_T
#define LAYERS 4
#define GROWS (LAYERS*4*DIM)       // 16384 stacked gate rows
#define NSTEP (NSAMP*LAYERS)       // 16384 sequential steps
#define NSLOT 441                  // 147 CTAs * 3 slots (3 h values + tag each)

// ---------------------------------------------------------------------------
// Scratch (static device globals; no runtime allocation)
// ---------------------------------------------------------------------------
__device__ float g_PE [(size_t)NSAMP*DIM];
__device__ float g_T1 [(size_t)NSAMP*DIM];
__device__ float g_EMB[(size_t)NSAMP*DIM];
__device__ float g_XP [(size_t)NSAMP*DIM];
__device__ float g_R  [(size_t)GROWS*NSAMP];   // 256 MB: R[row, i]
__device__ float g_H  [(size_t)NSAMP*DIM];
__device__ float g_BS [GROWS];
// Tagged-quad h exchange, double-buffered by step parity.
// Slot = {h0,h1,h2, tag}. Buffer b holds steps with (g&1)==b.
__device__ uint4 g_hx[2*NSLOT];

// ---------------------------------------------------------------------------
// 16B volatile vector ld/st (single L2 transaction carrying data + tag)
// ---------------------------------------------------------------------------
__device__ __forceinline__ uint4 ldv4(const uint4* p) {
    uint4 v;
    asm volatile("ld.volatile.global.v4.u32 {%0,%1,%2,%3}, [%4];"
                 : "=r"(v.x), "=r"(v.y), "=r"(v.z), "=r"(v.w) : "l"(p) : "memory");
    return v;
}
__device__ __forceinline__ void stv4(uint4* p, uint4 v) {
    asm volatile("st.volatile.global.v4.u32 [%0], {%1,%2,%3,%4};"
                 :: "l"(p), "r"(v.x), "r"(v.y), "r"(v.z), "r"(v.w) : "memory");
}

// ---------------------------------------------------------------------------
// Sinusoidal positional embedding
// ---------------------------------------------------------------------------
__global__ void pe_kernel(const int* __restrict__ ts, float* __restrict__ PE) {
    int i = blockIdx.x;
    float t = (float)ts[i];
    for (int d = threadIdx.x; d < DIM/2; d += blockDim.x) {
        float f = expf((float)d * (-9.210340371976184f / (float)(DIM/2 - 1)));
        float a = t * f;
        PE[(size_t)i*DIM + d]          = sinf(a);
        PE[(size_t)i*DIM + DIM/2 + d]  = cosf(a);
    }
}

__global__ void bias_kernel(const float* __restrict__ bih, const float* __restrict__ bhh,
                            float* __restrict__ out) {
    int idx = blockIdx.x*blockDim.x + threadIdx.x;
    if (idx < GROWS) out[idx] = bih[idx] + bhh[idx];
}

__global__ void reset_kernel() {
    int idx = blockIdx.x*blockDim.x + threadIdx.x;
    if (idx < 2*NSLOT) g_hx[idx] = make_uint4(0u, 0u, 0u, 0u);  // tag 0, h = 0
}

// ---------------------------------------------------------------------------
// Generic NT GEMM: C[m,n] = sum_k A[m,k]*B[n,k] (+biasM[m]) (+biasN[n]) (+add[m,n]) (silu)
// BM=BN=128, BK=16, 256 threads, 8x8 per thread, double-buffered SMEM.
// ---------------------------------------------------------------------------
__global__ __launch_bounds__(256, 2)
void gemm_nt(const float* __restrict__ A, const float* __restrict__ B,
             float* __restrict__ C, int M, int N, int K,
             const float* __restrict__ biasM, const float* __restrict__ biasN,
             const float* __restrict__ addMN, int do_silu)
{
    const int BM = 128, BK = 16;
    __shared__ float As[2][16][128+8];
    __shared__ float Bs[2][16][128+8];

    const int tid = threadIdx.x;
    const int m0 = blockIdx.y * BM, n0 = blockIdx.x * BM;
    const int tx = tid & 15, ty = tid >> 4;

    float4 aF[2], bF[2];

    #pragma unroll
    for (int i = 0; i < 2; i++) {
        int f = tid + i*256;
        int row = f >> 2, c4 = (f & 3) * 4;
        aF[i] = *(const float4*)&A[(size_t)(m0+row)*K + c4];
        bF[i] = *(const float4*)&B[(size_t)(n0+row)*K + c4];
    }
    #pragma unroll
    for (int i = 0; i < 2; i++) {
        int f = tid + i*256;
        int row = f >> 2, c4 = (f & 3) * 4;
        As[0][c4+0][row] = aF[i].x; As[0][c4+1][row] = aF[i].y;
        As[0][c4+2][row] = aF[i].z; As[0][c4+3][row] = aF[i].w;
        Bs[0][c4+0][row] = bF[i].x; Bs[0][c4+1][row] = bF[i].y;
        Bs[0][c4+2][row] = bF[i].z; Bs[0][c4+3][row] = bF[i].w;
    }
    __syncthreads();

    float acc[8][8];
    #pragma unroll
    for (int i = 0; i < 8; i++)
        #pragma unroll
        for (int j = 0; j < 8; j++) acc[i][j] = 0.f;

    const int nk = K / BK;
    for (int kt = 0; kt < nk; kt++) {
        const int cur = kt & 1;
        if (kt + 1 < nk) {
            int k0 = (kt+1)*BK;
            #pragma unroll
            for (int i = 0; i < 2; i++) {
                int f = tid + i*256;
                int row = f >> 2, c4 = (f & 3) * 4;
                aF[i] = *(const float4*)&A[(size_t)(m0+row)*K + k0 + c4];
                bF[i] = *(const float4*)&B[(size_t)(n0+row)*K + k0 + c4];
            }
        }
        #pragma unroll
        for (int k = 0; k < BK; k++) {
            float a[8], b[8];
            *(float4*)&a[0] = *(const float4*)&As[cur][k][ty*8];
            *(float4*)&a[4] = *(const float4*)&As[cur][k][ty*8+4];
            *(float4*)&b[0] = *(const float4*)&Bs[cur][k][tx*8];
            *(float4*)&b[4] = *(const float4*)&Bs[cur][k][tx*8+4];
            #pragma unroll
            for (int i = 0; i < 8; i++)
                #pragma unroll
                for (int j = 0; j < 8; j++)
                    acc[i][j] += a[i] * b[j];
        }
        if (kt + 1 < nk) {
            const int nxt = cur ^ 1;
            #pragma unroll
            for (int i = 0; i < 2; i++) {
                int f = tid + i*256;
                int row = f >> 2, c4 = (f & 3) * 4;
                As[nxt][c4+0][row] = aF[i].x; As[nxt][c4+1][row] = aF[i].y;
                As[nxt][c4+2][row] = aF[i].z; As[nxt][c4+3][row] = aF[i].w;
                Bs[nxt][c4+0][row] = bF[i].x; Bs[nxt][c4+1][row] = bF[i].y;
                Bs[nxt][c4+2][row] = bF[i].z; Bs[nxt][c4+3][row] = bF[i].w;
            }
            __syncthreads();
        }
    }

    #pragma unroll
    for (int i = 0; i < 8; i++) {
        int m = m0 + ty*8 + i;
        float bm = biasM ? biasM[m] : 0.f;
        #pragma unroll
        for (int j = 0; j < 8; j++) {
            int n = n0 + tx*8 + j;
            float v = acc[i][j] + bm;
            if (biasN) v += biasN[n];
            if (addMN) v += addMN[(size_t)m*N + n];
            if (do_silu) v = v / (1.f + __expf(-v));
            C[(size_t)m*N + n] = v;
        }
    }
}

// ---------------------------------------------------------------------------
// Persistent sequential-scan kernel.
// 147 CTAs x 128 threads. CTA k owns h indices [7k, min(7k+7,1024)).
// ---------------------------------------------------------------------------
#define SCAN_CTAS 147
#define SCAN_TPB  128
#define WS_HALFS  (LAYERS*28*1024)            // 114688 halves
#define WS_BYTES  (WS_HALFS*2)                // 229376 B
#define SCAN_SMEM (WS_BYTES + 2048 + (28+56)*4)   // + h_sm(fp16) + gdot + ga[2]

__device__ __forceinline__ float tanh_fast(float x) {
    float cx = fminf(fmaxf(x, -15.f), 15.f);
    float e  = __expf(2.f * cx);
    return __fdividef(e - 1.f, e + 1.f);
}
__device__ __forceinline__ float sigmoid_fast(float x) {
    return __fdividef(1.f, 1.f + __expf(-x));
}

__global__ __launch_bounds__(SCAN_TPB, 1)
void scan_kernel(const float* __restrict__ Whh, const float* __restrict__ R,
                 float* __restrict__ Hbuf)
{
    extern __shared__ unsigned char smem[];
    __half* ws   = (__half*)smem;                         // [(l*28+rl)*1024 + perm]
    __half* h_sm = (__half*)(smem + WS_BYTES);            // [1024] permuted
    float*  gdot = (float*)(smem + WS_BYTES + 2048);      // [28]
    float*  ga   = gdot + 28;                             // [2][28]

    const int cta = blockIdx.x, tid = threadIdx.x;
    const int j0  = cta * 7;
    const int nj  = (j0 + 7 <= DIM) ? 7 : (DIM - j0);     // last CTA: 2

    // ---- fill SMEM weights (fp16, permuted: lane reads wr[m8*256+lane*8+b] = k(lane*32+m8*8+b))
    for (int p = tid; p < WS_HALFS; p += SCAN_TPB) {
        int rowblk = p >> 10;                   // l*28 + rl
        int l  = rowblk / 28, rl = rowblk - l*28;
        int off = p & 1023;
        int m8 = off >> 8, ln = (off >> 3) & 31, b = off & 7;
        int q = rl / 7, u = rl - q*7;
        float v = 0.f;
        if (u < nj) {
            int k = ln*32 + m8*8 + b;
            v = Whh[((size_t)l*4*DIM + q*DIM + j0 + u)*DIM + k];
        }
        ws[p] = __float2half(v);
    }
    __syncthreads();

    const int w = tid >> 5, lane = tid & 31;
    float cst = 0.f;                             // c state (warp0 lane u only)

    // ---- per-thread poll-slot assignment (static)
    int nsl = 0;
    int      sid4[4];
    int      jb4 [4];
    int      dm4 [4];
    #pragma unroll
    for (int k = 0; k < 4; k++) {
        int s = tid + 128*k;
        if (s < NSLOT) {
            int cs = s / 3, r = s - 3*cs;
            int jb = cs*7 + r*3;
            if (jb < DIM) {
                int njc = (cs*7 + 7 <= DIM) ? 7 : (DIM - cs*7);
                int dm = njc - r*3; if (dm > 3) dm = 3;
                if (dm > 0) { sid4[nsl] = s; jb4[nsl] = jb; dm4[nsl] = dm; nsl++; }
            }
        }
    }

    // ---- R prefetch bookkeeping (one step ahead)
    int pf_q = 0, pf_u = 0;
    bool pf_act = (tid < 28);
    if (pf_act) { pf_q = tid / 7; pf_u = tid - pf_q*7; pf_act = (pf_u < nj); }
    float a_cur = 0.f;
    if (pf_act)   // step g=1: i=0, l=0
        a_cur = R[((size_t)(pf_q*DIM + j0 + pf_u))*NSAMP + 0];

    #pragma unroll 1
    for (int g = 1; g <= NSTEP; ++g) {
        const int s = g - 1;
        const int i = s >> 2, l = s & 3;

        // ---- issue next step's R prefetch (hides an entire step of latency)
        float a_nxt = 0.f;
        if (pf_act && g < NSTEP) {
            int i2 = g >> 2, l2 = g & 3;
            a_nxt = R[((size_t)(l2*4*DIM + pf_q*DIM + j0 + pf_u))*NSAMP + i2];
        }
        if (tid < 28) ga[(g & 1)*28 + tid] = a_cur;   // reg -> smem, no LDG dependency

        // ---- tagged-quad poll: data and tag arrive in one 16B transaction
        {
            const uint4* hb = g_hx + ((s & 1) * NSLOT);
            const unsigned want = (unsigned)s;     // accept tag >= s
            uint4 vv[4];
            bool ok;
            do {
                ok = true;
                #pragma unroll
                for (int k = 0; k < 4; k++) if (k < nsl) {
                    vv[k] = ldv4(hb + sid4[k]);
                    ok &= (vv[k].w >= want);
                }
            } while (!ok);
            #pragma unroll
            for (int k = 0; k < 4; k++) if (k < nsl) {
                unsigned dat[3] = { vv[k].x, vv[k].y, vv[k].z };
                #pragma unroll
                for (int d = 0; d < 3; d++) if (d < dm4[k]) {
                    int j = jb4[k] + d;
                    int p = ((j >> 3) & 3)*256 + (j >> 5)*8 + (j & 7);
                    h_sm[p] = __float2half(__uint_as_float(dat[d]));
                }
            }
        }
        __syncthreads();   // B1

        // ---- load h into registers: lane owns h[lane*32 .. +32)
        float hreg[32];
        #pragma unroll
        for (int m8 = 0; m8 < 4; m8++) {
            uint4 hv = *(const uint4*)&h_sm[m8*256 + lane*8];
            const __half2* h2 = (const __half2*)&hv;
            #pragma unroll
            for (int p2 = 0; p2 < 4; p2++) {
                float2 f = __half22float2(h2[p2]);
                hreg[m8*8 + p2*2]     = f.x;
                hreg[m8*8 + p2*2 + 1] = f.y;
            }
        }

        // ---- 7 rows per warp: rl = w + 4t
        float dotv[7];
        #pragma unroll
        for (int t = 0; t < 7; t++) {
            const int rl = w + 4*t;
            const __half* wr = ws + (((size_t)l*28 + rl) << 10);
            float acc = 0.f;
            #pragma unroll
            for (int m8 = 0; m8 < 4; m8++) {
                uint4 wv = *(const uint4*)&wr[m8*256 + lane*8];
                const __half2* w2 = (const __half2*)&wv;
                #pragma unroll
                for (int p2 = 0; p2 < 4; p2++) {
                    float2 wf = __half22float2(w2[p2]);
                    acc += wf.x * hreg[m8*8 + p2*2] + wf.y * hreg[m8*8 + p2*2 + 1];
                }
            }
            dotv[t] = acc;
        }
        #pragma unroll
        for (int t = 0; t < 7; t++) {
            float v = dotv[t];
            v += __shfl_xor_sync(0xffffffffu, v, 16);
            v += __shfl_xor_sync(0xffffffffu, v, 8);
            v += __shfl_xor_sync(0xffffffffu, v, 4);
            v += __shfl_xor_sync(0xffffffffu, v, 2);
            v += __shfl_xor_sync(0xffffffffu, v, 1);
            if (lane == 0) gdot[w + 4*t] = v;
        }
        __syncthreads();   // B2

        // ---- gate math + tagged-quad publish (warp 0)
        if (w == 0) {
            float h = 0.f;
            if (lane < nj) {
                const float* gav = ga + (g & 1)*28;
                float gi = gdot[lane]      + gav[lane];
                float gf = gdot[7 + lane]  + gav[7 + lane];
                float gg = gdot[14 + lane] + gav[14 + lane];
                float go = gdot[21 + lane] + gav[21 + lane];
                float I = sigmoid_fast(gi);
                float F = sigmoid_fast(gf);
                float G = tanh_fast(gg);
                cst = F * cst + I * G;
                float O = sigmoid_fast(go);
                h = O * tanh_fast(cst);
            }
            // pack 3 h values + tag per 16B slot; lanes 0..2 publish
            float p0 = __shfl_sync(0xffffffffu, h, (3*lane)     & 31);
            float p1 = __shfl_sync(0xffffffffu, h, (3*lane + 1) & 31);
            float p2 = __shfl_sync(0xffffffffu, h, (3*lane + 2) & 31);
            if (lane < 3 && 3*lane < nj) {
                uint4 pk;
                pk.x = __float_as_uint(p0);
                pk.y = __float_as_uint(p1);
                pk.z = __float_as_uint(p2);
                pk.w = (unsigned)g;
                stv4(&g_hx[(g & 1)*NSLOT + cta*3 + lane], pk);
            }
            if (lane < nj && l == 3)
                Hbuf[(size_t)i*DIM + j0 + lane] = h;
        }
        a_cur = a_nxt;
        // no trailing barrier: next step's poll self-synchronizes on tags
    }
}

// ---------------------------------------------------------------------------
// Launch
// ---------------------------------------------------------------------------
extern "C" void kernel_launch(void* const* d_in, const int* in_sizes, int n_in,
                              void* d_out, int out_size)
{
    const float* x      = (const float*)d_in[0];
    const int*   ts     = (const int*)  d_in[1];
    const float* proj_w = (const float*)d_in[2];
    const float* proj_b = (const float*)d_in[3];
    const float* te_w1  = (const float*)d_in[4];
    const float* te_b1  = (const float*)d_in[5];
    const float* te_w2  = (const float*)d_in[6];
    const float* te_b2  = (const float*)d_in[7];
    const float* Wih    = (const float*)d_in[8];
    const float* Whh    = (const float*)d_in[9];
    const float* bih    = (const float*)d_in[10];
    const float* bhh    = (const float*)d_in[11];
    const float* lin_w  = (const float*)d_in[12];
    const float* lin_b  = (const float*)d_in[13];
    float* out = (float*)d_out;

    float *PE, *T1, *EMB, *XP, *R, *H, *BS;
    cudaGetSymbolAddress((void**)&PE,  g_PE);
    cudaGetSymbolAddress((void**)&T1,  g_T1);
    cudaGetSymbolAddress((void**)&EMB, g_EMB);
    cudaGetSymbolAddress((void**)&XP,  g_XP);
    cudaGetSymbolAddress((void**)&R,   g_R);
    cudaGetSymbolAddress((void**)&H,   g_H);
    cudaGetSymbolAddress((void**)&BS,  g_BS);

    cudaFuncSetAttribute(scan_kernel, cudaFuncAttributeMaxDynamicSharedMemorySize,
                         SCAN_SMEM);

    // 1) sinusoidal PE
    pe_kernel<<<NSAMP, 128>>>(ts, PE);
    // 2) T1 = silu(PE @ te_w1^T + te_b1)
    gemm_nt<<<dim3(DIM/128, NSAMP/128), 256>>>(PE, te_w1, T1, NSAMP, DIM, DIM,
                                               nullptr, te_b1, nullptr, 1);
    // 3) EMB = T1 @ te_w2^T + te_b2
    gemm_nt<<<dim3(DIM/128, NSAMP/128), 256>>>(T1, te_w2, EMB, NSAMP, DIM, DIM,
                                               nullptr, te_b2, nullptr, 0);
    // 4) XP = x @ proj_w^T + proj_b + EMB
    gemm_nt<<<dim3(DIM/128, NSAMP/128), 256>>>(x, proj_w, XP, NSAMP, DIM, DIM,
                                               nullptr, proj_b, EMB, 0);
    // 5) stacked gate bias
    bias_kernel<<<GROWS/256, 256>>>(bih, bhh, BS);
    // 6) R = Wih_stack @ XP^T + bias   (16384 x 4096 x 1024)
    gemm_nt<<<dim3(NSAMP/128, GROWS/128), 256>>>(Wih, XP, R, GROWS, NSAMP, DIM,
                                                 BS, nullptr, nullptr, 0);
    // 7) reset tagged h buffers (graph-replay safe)
    reset_kernel<<<(2*NSLOT+255)/256, 256>>>();
    // 8) persistent sequential scan
    scan_kernel<<<SCAN_CTAS, SCAN_TPB, SCAN_SMEM>>>(Whh, R, H);
    // 9) out = H @ lin_w^T + lin_b
    gemm_nt<<<dim3(DIM/128, NSAMP/128), 256>>>(H, lin_w, out, NSAMP, DIM, DIM,
                                               nullptr, lin_b, nullptr, 0);
}